// round 1
// baseline (speedup 1.0000x reference)
#include <cuda_runtime.h>
#include <math.h>

#define NBINS 64
#define BATCH 4
#define NVOX 262144           // 64*64*64
#define HIST_SIZE (NBINS*NBINS)
#define HBLOCKS 128           // blocks per batch for hist kernel
#define HTHREADS 256

__device__ unsigned g_mm[4];                 // ordered-uint: tmin,tmax,smin,smax
__device__ float g_hist[BATCH * HIST_SIZE];  // per-batch joint histograms

// monotone float<->uint mapping (order-preserving for all floats)
__device__ __forceinline__ unsigned f2o(float f) {
    unsigned b = __float_as_uint(f);
    return (b & 0x80000000u) ? ~b : (b | 0x80000000u);
}
__device__ __forceinline__ float o2f(unsigned o) {
    return __uint_as_float((o & 0x80000000u) ? (o & 0x7FFFFFFFu) : ~o);
}

__global__ void init_kernel() {
    int tid = threadIdx.x;
    for (int i = tid; i < BATCH * HIST_SIZE; i += blockDim.x) g_hist[i] = 0.0f;
    if (tid < 2) {
        g_mm[2 * tid + 0] = 0xFFFFFFFFu;  // min accumulator (max ordered value)
        g_mm[2 * tid + 1] = 0x00000000u;  // max accumulator (min ordered value)
    }
}

__global__ void minmax_kernel(const float4* __restrict__ t,
                              const float4* __restrict__ s, int n4) {
    float tmn = INFINITY, tmx = -INFINITY, smn = INFINITY, smx = -INFINITY;
    for (int i = blockIdx.x * blockDim.x + threadIdx.x; i < n4;
         i += gridDim.x * blockDim.x) {
        float4 a = t[i];
        tmn = fminf(tmn, fminf(fminf(a.x, a.y), fminf(a.z, a.w)));
        tmx = fmaxf(tmx, fmaxf(fmaxf(a.x, a.y), fmaxf(a.z, a.w)));
        float4 b = s[i];
        smn = fminf(smn, fminf(fminf(b.x, b.y), fminf(b.z, b.w)));
        smx = fmaxf(smx, fmaxf(fmaxf(b.x, b.y), fmaxf(b.z, b.w)));
    }
#pragma unroll
    for (int o = 16; o > 0; o >>= 1) {
        tmn = fminf(tmn, __shfl_xor_sync(0xFFFFFFFFu, tmn, o));
        tmx = fmaxf(tmx, __shfl_xor_sync(0xFFFFFFFFu, tmx, o));
        smn = fminf(smn, __shfl_xor_sync(0xFFFFFFFFu, smn, o));
        smx = fmaxf(smx, __shfl_xor_sync(0xFFFFFFFFu, smx, o));
    }
    if ((threadIdx.x & 31) == 0) {
        atomicMin(&g_mm[0], f2o(tmn));
        atomicMax(&g_mm[1], f2o(tmx));
        atomicMin(&g_mm[2], f2o(smn));
        atomicMax(&g_mm[3], f2o(smx));
    }
}

// 4-tap cubic B-spline weights for fractional position f in [0,1):
// taps hit bins i0-1, i0, i0+1, i0+2 where i0 = floor(x), f = x - i0.
__device__ __forceinline__ void bsw(float f, float w[4]) {
    float omf = 1.0f - f;
    w[0] = omf * omf * omf * (1.0f / 6.0f);
    w[1] = (2.0f / 3.0f) - f * f + 0.5f * f * f * f;
    w[2] = (2.0f / 3.0f) - omf * omf + 0.5f * omf * omf * omf;
    w[3] = f * f * f * (1.0f / 6.0f);
}

__global__ void hist_kernel(const float* __restrict__ t,
                            const float* __restrict__ s) {
    __shared__ float sh[HIST_SIZE];
    const int b = blockIdx.y;
    for (int i = threadIdx.x; i < HIST_SIZE; i += blockDim.x) sh[i] = 0.0f;
    __syncthreads();

    const float tmn = o2f(g_mm[0]), tmx = o2f(g_mm[1]);
    const float smn = o2f(g_mm[2]), smx = o2f(g_mm[3]);
    const float tsc = 64.0f / (tmx - tmn + 1e-12f);
    const float ssc = 64.0f / (smx - smn + 1e-12f);

    const float4* tb = (const float4*)(t + (size_t)b * NVOX);
    const float4* sb = (const float4*)(s + (size_t)b * NVOX);
    const int n4 = NVOX / 4;

    for (int v = blockIdx.x * blockDim.x + threadIdx.x; v < n4;
         v += gridDim.x * blockDim.x) {
        float4 tv = tb[v];
        float4 sv = sb[v];
        float tvals[4] = {tv.x, tv.y, tv.z, tv.w};
        float svals[4] = {sv.x, sv.y, sv.z, sv.w};
#pragma unroll
        for (int k = 0; k < 4; k++) {
            float xt = (tvals[k] - tmn) * tsc;
            float xs = (svals[k] - smn) * ssc;
            int it = (int)floorf(xt);
            int is = (int)floorf(xs);
            float ft = xt - (float)it;
            float fs = xs - (float)is;
            float wt[4], ws[4];
            bsw(ft, wt);
            bsw(fs, ws);
#pragma unroll
            for (int a = 0; a < 4; a++) {
                int r = it - 1 + a;
                if ((unsigned)r >= (unsigned)NBINS) continue;
                float w = wt[a];
                int base = r * NBINS;
#pragma unroll
                for (int c = 0; c < 4; c++) {
                    int cc = is - 1 + c;
                    if ((unsigned)cc >= (unsigned)NBINS) continue;
                    atomicAdd(&sh[base + cc], w * ws[c]);
                }
            }
        }
    }
    __syncthreads();

    float* gh = g_hist + b * HIST_SIZE;
    for (int i = threadIdx.x; i < HIST_SIZE; i += blockDim.x) {
        float v = sh[i];
        if (v != 0.0f) atomicAdd(&gh[i], v);
    }
}

__global__ void final_kernel(float* __restrict__ out) {
    const int T = 256;
    __shared__ double red[T];
    __shared__ double marg[NBINS];
    const int tid = threadIdx.x;

    // global sum over all batches (scale by 1/EPS^2 cancels in p_joint)
    double s = 0.0;
    for (int i = tid; i < BATCH * HIST_SIZE; i += T) s += (double)g_hist[i];
    red[tid] = s;
    __syncthreads();
    for (int o = T / 2; o > 0; o >>= 1) {
        if (tid < o) red[tid] += red[tid + o];
        __syncthreads();
    }
    double S = red[0];
    __syncthreads();
    double inv = 1.0 / S;

    double total = 0.0;
    for (int b = 0; b < BATCH; b++) {
        const float* h = g_hist + b * HIST_SIZE;

        // joint entropy
        double hj = 0.0;
        for (int i = tid; i < HIST_SIZE; i += T) {
            double p = (double)h[i] * inv;
            hj += p * log(p + 1e-12);
        }
        red[tid] = hj;
        __syncthreads();
        for (int o = T / 2; o > 0; o >>= 1) {
            if (tid < o) red[tid] += red[tid + o];
            __syncthreads();
        }
        double Hj = -red[0];
        __syncthreads();

        // target marginal entropy (rows)
        if (tid < NBINS) {
            double r = 0.0;
            for (int j = 0; j < NBINS; j++) r += (double)h[tid * NBINS + j];
            marg[tid] = r * inv;
        }
        __syncthreads();
        {
            double e = 0.0;
            if (tid < NBINS) {
                double p = marg[tid];
                e = p * log(p + 1e-12);
            }
            red[tid] = e;
        }
        __syncthreads();
        for (int o = T / 2; o > 0; o >>= 1) {
            if (tid < o) red[tid] += red[tid + o];
            __syncthreads();
        }
        double Ht = -red[0];
        __syncthreads();

        // source marginal entropy (cols)
        if (tid < NBINS) {
            double r = 0.0;
            for (int j = 0; j < NBINS; j++) r += (double)h[j * NBINS + tid];
            marg[tid] = r * inv;
        }
        __syncthreads();
        {
            double e = 0.0;
            if (tid < NBINS) {
                double p = marg[tid];
                e = p * log(p + 1e-12);
            }
            red[tid] = e;
        }
        __syncthreads();
        for (int o = T / 2; o > 0; o >>= 1) {
            if (tid < o) red[tid] += red[tid + o];
            __syncthreads();
        }
        double Hs = -red[0];
        __syncthreads();

        total += (Ht + Hs) / Hj;
    }
    if (tid == 0) out[0] = (float)(-total / (double)BATCH);
}

extern "C" void kernel_launch(void* const* d_in, const int* in_sizes, int n_in,
                              void* d_out, int out_size) {
    const float* target = (const float*)d_in[0];
    const float* source = (const float*)d_in[1];
    float* out = (float*)d_out;

    init_kernel<<<1, 256>>>();
    minmax_kernel<<<256, 256>>>((const float4*)target, (const float4*)source,
                                BATCH * NVOX / 4);
    {
        dim3 grid(HBLOCKS, BATCH);
        hist_kernel<<<grid, HTHREADS>>>(target, source);
    }
    final_kernel<<<1, 256>>>(out);
}

// round 2
// speedup vs baseline: 1.2263x; 1.2263x over previous
#include <cuda_runtime.h>
#include <math.h>

#define NBINS 64
#define BATCH 4
#define NVOX 262144           // 64*64*64
#define HIST_SIZE (NBINS*NBINS)
#define HBLOCKS 128           // blocks per batch for hist kernel
#define HTHREADS 256
#define PROWS 68              // padded: rows/cols -1..66

__device__ unsigned g_mm[4];                 // ordered-uint: tmin,tmax,smin,smax
__device__ float g_hist[BATCH * HIST_SIZE];  // per-batch joint histograms

// monotone float<->uint mapping (order-preserving for all floats)
__device__ __forceinline__ unsigned f2o(float f) {
    unsigned b = __float_as_uint(f);
    return (b & 0x80000000u) ? ~b : (b | 0x80000000u);
}
__device__ __forceinline__ float o2f(unsigned o) {
    return __uint_as_float((o & 0x80000000u) ? (o & 0x7FFFFFFFu) : ~o);
}

__global__ void init_kernel() {
    int tid = threadIdx.x;
    for (int i = tid; i < BATCH * HIST_SIZE; i += blockDim.x) g_hist[i] = 0.0f;
    if (tid < 2) {
        g_mm[2 * tid + 0] = 0xFFFFFFFFu;  // min accumulator
        g_mm[2 * tid + 1] = 0x00000000u;  // max accumulator
    }
}

__global__ void minmax_kernel(const float4* __restrict__ t,
                              const float4* __restrict__ s, int n4) {
    float tmn = INFINITY, tmx = -INFINITY, smn = INFINITY, smx = -INFINITY;
    for (int i = blockIdx.x * blockDim.x + threadIdx.x; i < n4;
         i += gridDim.x * blockDim.x) {
        float4 a = t[i];
        tmn = fminf(tmn, fminf(fminf(a.x, a.y), fminf(a.z, a.w)));
        tmx = fmaxf(tmx, fmaxf(fmaxf(a.x, a.y), fmaxf(a.z, a.w)));
        float4 b = s[i];
        smn = fminf(smn, fminf(fminf(b.x, b.y), fminf(b.z, b.w)));
        smx = fmaxf(smx, fmaxf(fmaxf(b.x, b.y), fmaxf(b.z, b.w)));
    }
#pragma unroll
    for (int o = 16; o > 0; o >>= 1) {
        tmn = fminf(tmn, __shfl_xor_sync(0xFFFFFFFFu, tmn, o));
        tmx = fmaxf(tmx, __shfl_xor_sync(0xFFFFFFFFu, tmx, o));
        smn = fminf(smn, __shfl_xor_sync(0xFFFFFFFFu, smn, o));
        smx = fmaxf(smx, __shfl_xor_sync(0xFFFFFFFFu, smx, o));
    }
    if ((threadIdx.x & 31) == 0) {
        atomicMin(&g_mm[0], f2o(tmn));
        atomicMax(&g_mm[1], f2o(tmx));
        atomicMin(&g_mm[2], f2o(smn));
        atomicMax(&g_mm[3], f2o(smx));
    }
}

// 4-tap cubic B-spline weights for fractional position f in [0,1):
// taps hit bins i0-1, i0, i0+1, i0+2 where i0 = floor(x), f = x - i0.
__device__ __forceinline__ void bsw(float f, float w[4]) {
    float omf = 1.0f - f;
    w[0] = omf * omf * omf * (1.0f / 6.0f);
    w[1] = (2.0f / 3.0f) - f * f + 0.5f * f * f * f;
    w[2] = (2.0f / 3.0f) - omf * omf + 0.5f * omf * omf * omf;
    w[3] = f * f * f * (1.0f / 6.0f);
}

__global__ void hist_kernel(const float* __restrict__ t,
                            const float* __restrict__ s) {
    // padded 68x68: normalized coords in [0,64] -> taps in [-1,66]; the pad
    // rows/cols are exactly the bins the reference never evaluates, so
    // scattering into them and discarding is equivalent to branching.
    __shared__ float sh[PROWS * PROWS];
    const int b = blockIdx.y;
    for (int i = threadIdx.x; i < PROWS * PROWS; i += blockDim.x) sh[i] = 0.0f;
    __syncthreads();

    const float tmn = o2f(g_mm[0]), tmx = o2f(g_mm[1]);
    const float smn = o2f(g_mm[2]), smx = o2f(g_mm[3]);
    const float tsc = 64.0f / (tmx - tmn + 1e-12f);
    const float ssc = 64.0f / (smx - smn + 1e-12f);

    const float4* tb = (const float4*)(t + (size_t)b * NVOX);
    const float4* sb = (const float4*)(s + (size_t)b * NVOX);
    const int n4 = NVOX / 4;

    for (int v = blockIdx.x * blockDim.x + threadIdx.x; v < n4;
         v += gridDim.x * blockDim.x) {
        float4 tv = tb[v];
        float4 sv = sb[v];
        float tvals[4] = {tv.x, tv.y, tv.z, tv.w};
        float svals[4] = {sv.x, sv.y, sv.z, sv.w};
#pragma unroll
        for (int k = 0; k < 4; k++) {
            float xt = (tvals[k] - tmn) * tsc;
            float xs = (svals[k] - smn) * ssc;
            int it = (int)floorf(xt);
            int is = (int)floorf(xs);
            float ft = xt - (float)it;
            float fs = xs - (float)is;
            float wt[4], ws[4];
            bsw(ft, wt);
            bsw(fs, ws);
            // padded index of tap (a=0,c=0): row it-1 -> padded it, col is-1 -> padded is
            float* base = &sh[it * PROWS + is];
#pragma unroll
            for (int a = 0; a < 4; a++) {
                float w = wt[a];
                float* row = base + a * PROWS;
                atomicAdd(row + 0, w * ws[0]);
                atomicAdd(row + 1, w * ws[1]);
                atomicAdd(row + 2, w * ws[2]);
                atomicAdd(row + 3, w * ws[3]);
            }
        }
    }
    __syncthreads();

    float* gh = g_hist + b * HIST_SIZE;
    for (int i = threadIdx.x; i < HIST_SIZE; i += blockDim.x) {
        int r = i >> 6, c = i & 63;
        float v = sh[(r + 1) * PROWS + (c + 1)];
        if (v != 0.0f) atomicAdd(&gh[i], v);
    }
}

// ---------------- finalization: fp32, 512 threads, shfl reductions ----------

#define FT 512

__device__ __forceinline__ float blockReduceSum(float v, float* shtmp) {
#pragma unroll
    for (int o = 16; o > 0; o >>= 1) v += __shfl_xor_sync(0xFFFFFFFFu, v, o);
    int warp = threadIdx.x >> 5, lane = threadIdx.x & 31;
    if (lane == 0) shtmp[warp] = v;
    __syncthreads();
    if (warp == 0) {
        v = (lane < (FT >> 5)) ? shtmp[lane] : 0.0f;
#pragma unroll
        for (int o = 8; o > 0; o >>= 1) v += __shfl_xor_sync(0xFFFFFFFFu, v, o);
        if (lane == 0) shtmp[0] = v;
    }
    __syncthreads();
    v = shtmp[0];
    __syncthreads();
    return v;
}

__global__ void final_kernel(float* __restrict__ out) {
    __shared__ float shtmp[FT >> 5];
    const int tid = threadIdx.x;

    // global sum over all batches (1/EPS^2 scale cancels in p_joint)
    float s = 0.0f;
    for (int i = tid; i < BATCH * HIST_SIZE; i += FT) s += g_hist[i];
    float S = blockReduceSum(s, shtmp);
    float inv = 1.0f / S;

    float total = 0.0f;
    for (int b = 0; b < BATCH; b++) {
        const float* h = g_hist + b * HIST_SIZE;

        // joint entropy
        float hj = 0.0f;
        for (int i = tid; i < HIST_SIZE; i += FT) {
            float p = h[i] * inv;
            hj += p * logf(p + 1e-12f);
        }
        float Hj = -blockReduceSum(hj, shtmp);

        // marginal entropies: threads 0..63 own one row + one col each
        float e = 0.0f;
        if (tid < NBINS) {
            float rsum = 0.0f, csum = 0.0f;
            const float* rp = h + tid * NBINS;
#pragma unroll 8
            for (int j = 0; j < NBINS; j++) {
                rsum += rp[j];
                csum += h[j * NBINS + tid];
            }
            float pr = rsum * inv, pc = csum * inv;
            e = pr * logf(pr + 1e-12f) + pc * logf(pc + 1e-12f);
        }
        float HtHs = -blockReduceSum(e, shtmp);

        total += HtHs / Hj;
    }
    if (tid == 0) out[0] = -total / (float)BATCH;
}

extern "C" void kernel_launch(void* const* d_in, const int* in_sizes, int n_in,
                              void* d_out, int out_size) {
    const float* target = (const float*)d_in[0];
    const float* source = (const float*)d_in[1];
    float* out = (float*)d_out;

    init_kernel<<<1, 256>>>();
    minmax_kernel<<<256, 256>>>((const float4*)target, (const float4*)source,
                                BATCH * NVOX / 4);
    {
        dim3 grid(HBLOCKS, BATCH);
        hist_kernel<<<grid, HTHREADS>>>(target, source);
    }
    final_kernel<<<1, FT>>>(out);
}

// round 4
// speedup vs baseline: 1.4551x; 1.1866x over previous
#include <cuda_runtime.h>
#include <math.h>

#define NBINS 64
#define BATCH 4
#define NVOX 262144           // 64*64*64
#define HIST_SIZE (NBINS*NBINS)
#define HBLOCKS 128           // blocks per batch for hist kernel
#define HTHREADS 256
#define PROWS 68              // padded hist rows/cols: -1..66
#define NREP 2                // shared-hist replicas

__device__ unsigned g_mm[4];                 // ordered-uint: tmin,tmax,smin,smax
__device__ float g_hist[BATCH * HIST_SIZE];  // per-batch joint histograms

__device__ __forceinline__ unsigned f2o(float f) {
    unsigned b = __float_as_uint(f);
    return (b & 0x80000000u) ? ~b : (b | 0x80000000u);
}
__device__ __forceinline__ float o2f(unsigned o) {
    return __uint_as_float((o & 0x80000000u) ? (o & 0x7FFFFFFFu) : ~o);
}

__global__ void init_kernel() {
    int tid = threadIdx.x;
    for (int i = tid; i < BATCH * HIST_SIZE; i += blockDim.x) g_hist[i] = 0.0f;
    if (tid < 2) {
        g_mm[2 * tid + 0] = 0xFFFFFFFFu;  // min accumulator
        g_mm[2 * tid + 1] = 0x00000000u;  // max accumulator
    }
}

__global__ void minmax_kernel(const float4* __restrict__ t,
                              const float4* __restrict__ s, int n4) {
    float tmn = INFINITY, tmx = -INFINITY, smn = INFINITY, smx = -INFINITY;
    for (int i = blockIdx.x * blockDim.x + threadIdx.x; i < n4;
         i += gridDim.x * blockDim.x) {
        float4 a = t[i];
        tmn = fminf(tmn, fminf(fminf(a.x, a.y), fminf(a.z, a.w)));
        tmx = fmaxf(tmx, fmaxf(fmaxf(a.x, a.y), fmaxf(a.z, a.w)));
        float4 b = s[i];
        smn = fminf(smn, fminf(fminf(b.x, b.y), fminf(b.z, b.w)));
        smx = fmaxf(smx, fmaxf(fmaxf(b.x, b.y), fmaxf(b.z, b.w)));
    }
#pragma unroll
    for (int o = 16; o > 0; o >>= 1) {
        tmn = fminf(tmn, __shfl_xor_sync(0xFFFFFFFFu, tmn, o));
        tmx = fmaxf(tmx, __shfl_xor_sync(0xFFFFFFFFu, tmx, o));
        smn = fminf(smn, __shfl_xor_sync(0xFFFFFFFFu, smn, o));
        smx = fmaxf(smx, __shfl_xor_sync(0xFFFFFFFFu, smx, o));
    }
    if ((threadIdx.x & 31) == 0) {
        atomicMin(&g_mm[0], f2o(tmn));
        atomicMax(&g_mm[1], f2o(tmx));
        atomicMin(&g_mm[2], f2o(smn));
        atomicMax(&g_mm[3], f2o(smx));
    }
}

// 4-tap cubic B-spline weights for fractional position f in [0,1).
__device__ __forceinline__ void bsw(float f, float w[4]) {
    float omf = 1.0f - f;
    w[0] = omf * omf * omf * (1.0f / 6.0f);
    w[1] = (2.0f / 3.0f) - f * f + 0.5f * f * f * f;
    w[2] = (2.0f / 3.0f) - omf * omf + 0.5f * omf * omf * omf;
    w[3] = f * f * f * (1.0f / 6.0f);
}

__global__ void hist_kernel(const float* __restrict__ t,
                            const float* __restrict__ s) {
    // 2 replicated padded histograms; warps alternate replicas to halve
    // shared-atomic conflicts. Pad rows/cols hold the taps the reference
    // clips (normalized coords in [0,64] -> taps in [-1,66]).
    __shared__ float sh[NREP][PROWS * PROWS];
    const int b = blockIdx.y;
    for (int i = threadIdx.x; i < NREP * PROWS * PROWS; i += blockDim.x)
        sh[0][i] = 0.0f;
    __syncthreads();

    const float tmn = o2f(g_mm[0]), tmx = o2f(g_mm[1]);
    const float smn = o2f(g_mm[2]), smx = o2f(g_mm[3]);
    const float tsc = 64.0f / (tmx - tmn + 1e-12f);
    const float ssc = 64.0f / (smx - smn + 1e-12f);

    const float4* tb = (const float4*)(t + (size_t)b * NVOX);
    const float4* sb = (const float4*)(s + (size_t)b * NVOX);
    const int n4 = NVOX / 4;

    float* my = sh[(threadIdx.x >> 5) & (NREP - 1)];

    for (int v = blockIdx.x * blockDim.x + threadIdx.x; v < n4;
         v += gridDim.x * blockDim.x) {
        float4 tv = tb[v];
        float4 sv = sb[v];
        float tvals[4] = {tv.x, tv.y, tv.z, tv.w};
        float svals[4] = {sv.x, sv.y, sv.z, sv.w};
#pragma unroll
        for (int k = 0; k < 4; k++) {
            float xt = (tvals[k] - tmn) * tsc;
            float xs = (svals[k] - smn) * ssc;
            int it = (int)floorf(xt);
            int is = (int)floorf(xs);
            float ft = xt - (float)it;
            float fs = xs - (float)is;
            float wt[4], ws[4];
            bsw(ft, wt);
            bsw(fs, ws);
            float* base = &my[it * PROWS + is];
#pragma unroll
            for (int a = 0; a < 4; a++) {
                float w = wt[a];
                float* row = base + a * PROWS;
                atomicAdd(row + 0, w * ws[0]);
                atomicAdd(row + 1, w * ws[1]);
                atomicAdd(row + 2, w * ws[2]);
                atomicAdd(row + 3, w * ws[3]);
            }
        }
    }
    __syncthreads();

    float* gh = g_hist + b * HIST_SIZE;
    for (int i = threadIdx.x; i < HIST_SIZE; i += blockDim.x) {
        int r = i >> 6, c = i & 63;
        int p = (r + 1) * PROWS + (c + 1);
        float v = sh[0][p] + sh[1][p];
        if (v != 0.0f) atomicAdd(&gh[i], v);
    }
}

// ---------------- finalization: shared-staged, fp32, 512 threads ------------

#define FT 512
#define LROW 65  // padded shared row to avoid bank conflicts on column sums

__device__ __forceinline__ float blockReduceSum(float v, float* shtmp) {
#pragma unroll
    for (int o = 16; o > 0; o >>= 1) v += __shfl_xor_sync(0xFFFFFFFFu, v, o);
    int warp = threadIdx.x >> 5, lane = threadIdx.x & 31;
    if (lane == 0) shtmp[warp] = v;
    __syncthreads();
    if (warp == 0) {
        v = (lane < (FT >> 5)) ? shtmp[lane] : 0.0f;
#pragma unroll
        for (int o = 8; o > 0; o >>= 1) v += __shfl_xor_sync(0xFFFFFFFFu, v, o);
        if (lane == 0) shtmp[0] = v;
    }
    __syncthreads();
    v = shtmp[0];
    __syncthreads();
    return v;
}

__global__ void final_kernel(float* __restrict__ out) {
    __shared__ float shh[NBINS * LROW];  // one batch's hist, padded rows
    __shared__ float shtmp[FT >> 5];
    const int tid = threadIdx.x;

    // global sum over all batches (1/EPS^2 cancels in p_joint)
    float s = 0.0f;
    {
        const float4* g4 = (const float4*)g_hist;
        for (int i = tid; i < BATCH * HIST_SIZE / 4; i += FT) {
            float4 v = g4[i];
            s += (v.x + v.y) + (v.z + v.w);
        }
    }
    float S = blockReduceSum(s, shtmp);
    float inv = 1.0f / S;

    float total = 0.0f;
    for (int b = 0; b < BATCH; b++) {
        // stage batch hist into shared (coalesced)
        const float4* g4 = (const float4*)(g_hist + b * HIST_SIZE);
        for (int i = tid; i < HIST_SIZE / 4; i += FT) {
            float4 v = g4[i];
            int r = i >> 4, c4 = (i & 15) << 2;  // 16 float4 per 64-wide row
            float* dst = &shh[r * LROW + c4];
            dst[0] = v.x; dst[1] = v.y; dst[2] = v.z; dst[3] = v.w;
        }
        __syncthreads();

        // joint entropy: 8 elements per thread from shared
        float hj = 0.0f;
#pragma unroll
        for (int q = 0; q < HIST_SIZE / FT; q++) {
            int i = q * FT + tid;
            int r = i >> 6, c = i & 63;
            float p = shh[r * LROW + c] * inv;
            hj += p * logf(p + 1e-12f);
        }
        float Hj = -blockReduceSum(hj, shtmp);

        // marginals: 64 rows x 8 threads each (8-lane groups within a warp)
        int r = tid >> 3, g = tid & 7;
        float rsum = 0.0f, csum = 0.0f;
#pragma unroll
        for (int j = 0; j < 8; j++) {
            rsum += shh[r * LROW + (g * 8 + j)];       // row r
            csum += shh[(g * 8 + j) * LROW + r];       // col r
        }
#pragma unroll
        for (int o = 1; o < 8; o <<= 1) {
            rsum += __shfl_xor_sync(0xFFFFFFFFu, rsum, o);
            csum += __shfl_xor_sync(0xFFFFFFFFu, csum, o);
        }
        float e = 0.0f;
        if (g == 0) {
            float pr = rsum * inv, pc = csum * inv;
            e = pr * logf(pr + 1e-12f) + pc * logf(pc + 1e-12f);
        }
        float HtHs = -blockReduceSum(e, shtmp);

        total += HtHs / Hj;
        __syncthreads();
    }
    if (tid == 0) out[0] = -total / (float)BATCH;
}

extern "C" void kernel_launch(void* const* d_in, const int* in_sizes, int n_in,
                              void* d_out, int out_size) {
    const float* target = (const float*)d_in[0];
    const float* source = (const float*)d_in[1];
    float* out = (float*)d_out;

    init_kernel<<<1, 256>>>();
    minmax_kernel<<<256, 256>>>((const float4*)target, (const float4*)source,
                                BATCH * NVOX / 4);
    {
        dim3 grid(HBLOCKS, BATCH);
        hist_kernel<<<grid, HTHREADS>>>(target, source);
    }
    final_kernel<<<1, FT>>>(out);
}